// round 9
// baseline (speedup 1.0000x reference)
#include <cuda_runtime.h>

#define NSAMP 8192
#define NOPT  16
#define DIM   768
#define NPAIR 136          // 16*17/2 upper-triangular incl. diagonal
#define MARGIN 0.3f
#define NEG_INF -1e9f

// Deterministic per-sample scratch (no device-side allocation allowed).
__device__ float g_loss[NSAMP];
__device__ float g_cnt[NSAMP];
__device__ int   g_lab_is32;   // 1 if labels buffer is int32, 0 if int64

__device__ __forceinline__ constexpr int triu_idx(int n, int m) {
    // n <= m required. Pairs of row n start at 16n - n(n-1)/2.
    return n * 16 - (n * (n - 1)) / 2 + (m - n);
}

// Dtype probe: view labels as int32 words. If the true dtype is int32 with
// values in {0,1}, odd-indexed words are nonzero ~half the time. If the true
// dtype is int64 (values 0/1, little-endian), odd words are hi-words == 0.
// Scanning 8192 words is safe under both layouts (buffer holds >= 131072
// int32 words either way) and misclassifies with prob ~2^-2048.
__global__ void detect_labels_kernel(const int* __restrict__ lab32)
{
    __shared__ int sany[256];
    const int t = threadIdx.x;
    int any = 0;
    for (int i = t * 2 + 1; i < 8192; i += 512)   // odd indices only
        any |= lab32[i];
    sany[t] = any;
    __syncthreads();
    for (int stride = 128; stride > 0; stride >>= 1) {
        if (t < stride) sany[t] |= sany[t + stride];
        __syncthreads();
    }
    if (t == 0) g_lab_is32 = (sany[0] != 0) ? 1 : 0;
}

// One warp per sample. Lane l owns k = 32*c + l. Each lane accumulates all 136
// pair partial dot-products in registers; butterfly-reduce across lanes at end.
__global__ __launch_bounds__(128, 3)
void gram_kernel(const float* __restrict__ emb, const void* __restrict__ labels_raw)
{
    const int warp = threadIdx.x >> 5;
    const int lane = threadIdx.x & 31;
    const int sample = blockIdx.x * 4 + warp;

    const float* base = emb + (size_t)sample * (NOPT * DIM);

    // Build pos/neg bitmasks (lanes 0..15 read one label each, dtype-robust).
    const int is32 = g_lab_is32;
    long long lab = -1ll;
    if (lane < NOPT) {
        const size_t idx = (size_t)sample * NOPT + lane;
        if (is32)
            lab = (long long)((const int*)labels_raw)[idx];
        else
            lab = ((const long long*)labels_raw)[idx];
    }
    const unsigned pos_mask = __ballot_sync(0xffffffffu, (lane < NOPT) && (lab == 1));
    const unsigned neg_mask = __ballot_sync(0xffffffffu, (lane < NOPT) && (lab == 0));

    float acc[NPAIR];
#pragma unroll
    for (int i = 0; i < NPAIR; ++i) acc[i] = 0.0f;

    const float* p = base + lane;
#pragma unroll 1
    for (int c = 0; c < DIM / 32; ++c) {
        float x[NOPT];
#pragma unroll
        for (int n = 0; n < NOPT; ++n)
            x[n] = __ldcs(p + n * DIM + c * 32);   // coalesced 128B per row, streaming
#pragma unroll
        for (int n = 0; n < NOPT; ++n) {
#pragma unroll
            for (int m = n; m < NOPT; ++m)
                acc[triu_idx(n, m)] = fmaf(x[n], x[m], acc[triu_idx(n, m)]);
        }
    }

    // Reduce each pair-sum across the 32 lanes; park results in smem so the
    // epilogue can index them dynamically without spilling a register array.
    __shared__ float ssum[4][NPAIR];
    float* s = ssum[warp];
#pragma unroll
    for (int i = 0; i < NPAIR; ++i) {
        float v = acc[i];
        v += __shfl_xor_sync(0xffffffffu, v, 16);
        v += __shfl_xor_sync(0xffffffffu, v, 8);
        v += __shfl_xor_sync(0xffffffffu, v, 4);
        v += __shfl_xor_sync(0xffffffffu, v, 2);
        v += __shfl_xor_sync(0xffffffffu, v, 1);
        if (lane == 0) s[i] = v;
    }
    __syncwarp();

    // Inverse norms: lane m computes its own, then broadcast-gather all 16.
    float inv_own = 0.0f;
    if (lane < NOPT) {
        float nrm = sqrtf(s[triu_idx(lane, lane)]);
        inv_own = 1.0f / fmaxf(nrm, 1e-12f);
    }
    float inv[NOPT];
#pragma unroll
    for (int m = 0; m < NOPT; ++m)
        inv[m] = __shfl_sync(0xffffffffu, inv_own, m);

    const bool valid = (pos_mask != 0u) && (neg_mask != 0u);

    // Lane n handles row n: max cosine sim against negative columns.
    float triplet = 0.0f;
    if (lane < NOPT && valid && ((pos_mask >> lane) & 1u)) {
        float mx = NEG_INF;
#pragma unroll
        for (int m = 0; m < NOPT; ++m) {
            if ((neg_mask >> m) & 1u) {
                int a = lane < m ? lane : m;
                int b = lane < m ? m : lane;
                float sim = s[triu_idx(a, b)] * inv[lane] * inv[m];
                mx = fmaxf(mx, sim);
            }
        }
        triplet = fmaxf(mx + MARGIN, 0.0f);
    }

    // Warp-sum triplet contributions.
    float tsum = triplet;
    tsum += __shfl_xor_sync(0xffffffffu, tsum, 16);
    tsum += __shfl_xor_sync(0xffffffffu, tsum, 8);
    tsum += __shfl_xor_sync(0xffffffffu, tsum, 4);
    tsum += __shfl_xor_sync(0xffffffffu, tsum, 2);
    tsum += __shfl_xor_sync(0xffffffffu, tsum, 1);

    if (lane == 0) {
        g_loss[sample] = tsum;
        g_cnt[sample]  = valid ? (float)__popc(pos_mask) : 0.0f;
    }
}

// Fixed-tree deterministic global reduction: out = sum(loss) / max(sum(count), 1)
__global__ void reduce_kernel(float* __restrict__ out)
{
    __shared__ float sl[256];
    __shared__ float sc[256];
    const int t = threadIdx.x;
    float ls = 0.0f, cs = 0.0f;
    for (int i = t; i < NSAMP; i += 256) {
        ls += g_loss[i];
        cs += g_cnt[i];
    }
    sl[t] = ls; sc[t] = cs;
    __syncthreads();
    for (int stride = 128; stride > 0; stride >>= 1) {
        if (t < stride) { sl[t] += sl[t + stride]; sc[t] += sc[t + stride]; }
        __syncthreads();
    }
    if (t == 0)
        out[0] = sl[0] / fmaxf(sc[0], 1.0f);
}

extern "C" void kernel_launch(void* const* d_in, const int* in_sizes, int n_in,
                              void* d_out, int out_size)
{
    const float* emb = (const float*)d_in[0];  // [8192, 16, 768] float32
    const void* labels = d_in[1];              // [8192, 16] int32 or int64 (probed)
    float* out = (float*)d_out;                // scalar float32

    (void)in_sizes; (void)n_in; (void)out_size;

    detect_labels_kernel<<<1, 256>>>((const int*)labels);
    gram_kernel<<<NSAMP / 4, 128>>>(emb, labels);
    reduce_kernel<<<1, 256>>>(out);
}